// round 6
// baseline (speedup 1.0000x reference)
#include <cuda_runtime.h>
#include <stdint.h>

// out[n] where n = pixel*3 + k  equals  image[pixel*3 + perm[n]]
// perm values are in {0,1,2} (per-pixel channel permutation).
//
// Each thread processes 4 pixels = 12 elements = 3 x float4 (image),
// 3 x int4 (perm), 3 x float4 (out). Channel selection is done with
// positional ternaries so everything stays in registers (no local mem).

static __device__ __forceinline__ float sel3(int p, float a, float b, float c) {
    // p in {0,1,2}
    return (p == 0) ? a : ((p == 1) ? b : c);
}

__global__ void __launch_bounds__(256)
perpixel_perm_kernel(const float4* __restrict__ img4,
                     const int4*   __restrict__ prm4,
                     float4*       __restrict__ out4,
                     int n_quads /* number of 4-pixel groups */) {
    int t = blockIdx.x * blockDim.x + threadIdx.x;
    if (t >= n_quads) return;

    const int base = t * 3;

    // 12 image floats covering 4 pixels
    float4 v0 = __ldg(&img4[base + 0]);
    float4 v1 = __ldg(&img4[base + 1]);
    float4 v2 = __ldg(&img4[base + 2]);

    // 12 perm ints covering 4 pixels
    int4 q0 = __ldg(&prm4[base + 0]);
    int4 q1 = __ldg(&prm4[base + 1]);
    int4 q2 = __ldg(&prm4[base + 2]);

    // Pixel 0: channels (v0.x, v0.y, v0.z), perms (q0.x, q0.y, q0.z)
    // Pixel 1: channels (v0.w, v1.x, v1.y), perms (q0.w, q1.x, q1.y)
    // Pixel 2: channels (v1.z, v1.w, v2.x), perms (q1.z, q1.w, q2.x)
    // Pixel 3: channels (v2.y, v2.z, v2.w), perms (q2.y, q2.z, q2.w)

    float4 o0, o1, o2;

    // outputs 0..3
    o0.x = sel3(q0.x, v0.x, v0.y, v0.z);
    o0.y = sel3(q0.y, v0.x, v0.y, v0.z);
    o0.z = sel3(q0.z, v0.x, v0.y, v0.z);
    o0.w = sel3(q0.w, v0.w, v1.x, v1.y);

    // outputs 4..7
    o1.x = sel3(q1.x, v0.w, v1.x, v1.y);
    o1.y = sel3(q1.y, v0.w, v1.x, v1.y);
    o1.z = sel3(q1.z, v1.z, v1.w, v2.x);
    o1.w = sel3(q1.w, v1.z, v1.w, v2.x);

    // outputs 8..11
    o2.x = sel3(q2.x, v1.z, v1.w, v2.x);
    o2.y = sel3(q2.y, v2.y, v2.z, v2.w);
    o2.z = sel3(q2.z, v2.y, v2.z, v2.w);
    o2.w = sel3(q2.w, v2.y, v2.z, v2.w);

    out4[base + 0] = o0;
    out4[base + 1] = o1;
    out4[base + 2] = o2;
}

extern "C" void kernel_launch(void* const* d_in, const int* in_sizes, int n_in,
                              void* d_out, int out_size) {
    const float* image = (const float*)d_in[0];
    const int*   perm  = (const int*)d_in[1];
    float*       out   = (float*)d_out;

    const int n_elems = in_sizes[0];       // 4096*4096*3 = 50331648, divisible by 12
    const int n_quads = n_elems / 12;      // 4,194,304 threads

    const int threads = 256;
    const int blocks  = (n_quads + threads - 1) / threads;

    perpixel_perm_kernel<<<blocks, threads>>>(
        (const float4*)image, (const int4*)perm, (float4*)out, n_quads);
}

// round 7
// speedup vs baseline: 1.0011x; 1.0011x over previous
#include <cuda_runtime.h>
#include <stdint.h>

// out[n] where n = pixel*3 + k  equals  image[pixel*3 + perm[n]]
// perm values are in {0,1,2} (per-pixel channel permutation).
//
// Each thread processes 4 pixels = 12 elements = 3 x float4 (image),
// 3 x int4 (perm), 3 x float4 (out). Channel selection is done with
// positional ternaries so everything stays in registers (no local mem).

static __device__ __forceinline__ float sel3(int p, float a, float b, float c) {
    // p in {0,1,2}
    return (p == 0) ? a : ((p == 1) ? b : c);
}

__global__ void __launch_bounds__(256)
perpixel_perm_kernel(const float4* __restrict__ img4,
                     const int4*   __restrict__ prm4,
                     float4*       __restrict__ out4,
                     int n_quads /* number of 4-pixel groups */) {
    int t = blockIdx.x * blockDim.x + threadIdx.x;
    if (t >= n_quads) return;

    const int base = t * 3;

    // 12 image floats covering 4 pixels
    float4 v0 = __ldg(&img4[base + 0]);
    float4 v1 = __ldg(&img4[base + 1]);
    float4 v2 = __ldg(&img4[base + 2]);

    // 12 perm ints covering 4 pixels
    int4 q0 = __ldg(&prm4[base + 0]);
    int4 q1 = __ldg(&prm4[base + 1]);
    int4 q2 = __ldg(&prm4[base + 2]);

    // Pixel 0: channels (v0.x, v0.y, v0.z), perms (q0.x, q0.y, q0.z)
    // Pixel 1: channels (v0.w, v1.x, v1.y), perms (q0.w, q1.x, q1.y)
    // Pixel 2: channels (v1.z, v1.w, v2.x), perms (q1.z, q1.w, q2.x)
    // Pixel 3: channels (v2.y, v2.z, v2.w), perms (q2.y, q2.z, q2.w)

    float4 o0, o1, o2;

    // outputs 0..3
    o0.x = sel3(q0.x, v0.x, v0.y, v0.z);
    o0.y = sel3(q0.y, v0.x, v0.y, v0.z);
    o0.z = sel3(q0.z, v0.x, v0.y, v0.z);
    o0.w = sel3(q0.w, v0.w, v1.x, v1.y);

    // outputs 4..7
    o1.x = sel3(q1.x, v0.w, v1.x, v1.y);
    o1.y = sel3(q1.y, v0.w, v1.x, v1.y);
    o1.z = sel3(q1.z, v1.z, v1.w, v2.x);
    o1.w = sel3(q1.w, v1.z, v1.w, v2.x);

    // outputs 8..11
    o2.x = sel3(q2.x, v1.z, v1.w, v2.x);
    o2.y = sel3(q2.y, v2.y, v2.z, v2.w);
    o2.z = sel3(q2.z, v2.y, v2.z, v2.w);
    o2.w = sel3(q2.w, v2.y, v2.z, v2.w);

    out4[base + 0] = o0;
    out4[base + 1] = o1;
    out4[base + 2] = o2;
}

extern "C" void kernel_launch(void* const* d_in, const int* in_sizes, int n_in,
                              void* d_out, int out_size) {
    const float* image = (const float*)d_in[0];
    const int*   perm  = (const int*)d_in[1];
    float*       out   = (float*)d_out;

    const int n_elems = in_sizes[0];       // 4096*4096*3 = 50331648, divisible by 12
    const int n_quads = n_elems / 12;      // 4,194,304 threads

    const int threads = 256;
    const int blocks  = (n_quads + threads - 1) / threads;

    perpixel_perm_kernel<<<blocks, threads>>>(
        (const float4*)image, (const int4*)perm, (float4*)out, n_quads);
}